// round 6
// baseline (speedup 1.0000x reference)
#include <cuda_runtime.h>
#include <cuda_bf16.h>
#include <cuda_fp16.h>
#include <cstdint>
#include <cstddef>

#define NN 100000
#define NPAD 100096   // 782 * 128
#define NE 1600000
#define C 128
#define NB_SCAN 98    // ceil(NN / 1024)

// ---------------- scratch (device globals) ----------------
__device__ int   g_deg[NN];
__device__ int   g_ptr[NN + 1];
__device__ int   g_cursor[NN];
__device__ float g_invc[NN];
__device__ int   g_csr[NE];
__device__ int   g_bsum[128];
__device__ float g_p1 [(size_t)NPAD * C];
__device__ float g_p2 [(size_t)NPAD * C];

__device__ __half g_xf16 [(size_t)NPAD * C];
__device__ __half g_h1f16[(size_t)NPAD * C];

__device__ __nv_bfloat16 g_xh [(size_t)NPAD * C];
__device__ __nv_bfloat16 g_xl [(size_t)NPAD * C];
__device__ __nv_bfloat16 g_aggh[(size_t)NPAD * C];
__device__ __nv_bfloat16 g_aggl[(size_t)NPAD * C];
__device__ __nv_bfloat16 g_h1h[(size_t)NPAD * C];
__device__ __nv_bfloat16 g_h1l[(size_t)NPAD * C];
__device__ __nv_bfloat16 g_h2h[(size_t)NPAD * C];
__device__ __nv_bfloat16 g_h2l[(size_t)NPAD * C];

// weights: 5 pairs (w1l, w1r, w2l, w2r, wd), each [n=128][k=128], hi+lo
__device__ __nv_bfloat16 g_wh[5][128 * 128];
__device__ __nv_bfloat16 g_wl[5][128 * 128];

// ---------------- helpers ----------------
__device__ __forceinline__ uint32_t s2u(const void* p) {
    uint32_t a;
    asm("{ .reg .u64 t; cvta.to.shared.u64 t, %1; cvt.u32.u64 %0, t; }" : "=r"(a) : "l"(p));
    return a;
}
__device__ __forceinline__ void split1(float v, __nv_bfloat16& h, __nv_bfloat16& l) {
    h = __float2bfloat16(v);
    l = __float2bfloat16(v - __bfloat162float(h));
}
__device__ __forceinline__ void ldsm4(uint32_t* r, uint32_t addr) {
    asm volatile("ldmatrix.sync.aligned.m8n8.x4.shared.b16 {%0,%1,%2,%3}, [%4];"
                 : "=r"(r[0]), "=r"(r[1]), "=r"(r[2]), "=r"(r[3]) : "r"(addr));
}
__device__ __forceinline__ void mma16816(float* d, const uint32_t* a, const uint32_t* b) {
    asm volatile(
        "mma.sync.aligned.m16n8k16.row.col.f32.bf16.bf16.f32 "
        "{%0,%1,%2,%3}, {%4,%5,%6,%7}, {%8,%9}, {%0,%1,%2,%3};"
        : "+f"(d[0]), "+f"(d[1]), "+f"(d[2]), "+f"(d[3])
        : "r"(a[0]), "r"(a[1]), "r"(a[2]), "r"(a[3]), "r"(b[0]), "r"(b[1]));
}
__device__ __forceinline__ uint32_t swz64(uint32_t off) {
    return off ^ ((off >> 3) & 0x30u);
}
__device__ __forceinline__ void cp16(uint32_t saddr, const void* gaddr) {
    asm volatile("cp.async.cg.shared.global [%0], [%1], 16;" :: "r"(saddr), "l"(gaddr));
}

// ---------------- CSR build ----------------
__global__ void count_kernel(const int* __restrict__ dst) {
    int e = blockIdx.x * blockDim.x + threadIdx.x;
    if (e < NE) atomicAdd(&g_deg[dst[e]], 1);
}
__global__ void scan1_kernel() {
    __shared__ int wsum[32];
    const int lane = threadIdx.x & 31;
    const int wid  = threadIdx.x >> 5;
    int i = blockIdx.x * 1024 + threadIdx.x;
    int v = (i < NN) ? g_deg[i] : 0;
    int incl = v;
    #pragma unroll
    for (int o = 1; o < 32; o <<= 1) {
        int t = __shfl_up_sync(0xFFFFFFFFu, incl, o);
        if (lane >= o) incl += t;
    }
    if (lane == 31) wsum[wid] = incl;
    __syncthreads();
    if (wid == 0) {
        int ws = wsum[lane];
        int wi = ws;
        #pragma unroll
        for (int o = 1; o < 32; o <<= 1) {
            int t = __shfl_up_sync(0xFFFFFFFFu, wi, o);
            if (lane >= o) wi += t;
        }
        wsum[lane] = wi - ws;
    }
    __syncthreads();
    int excl = wsum[wid] + incl - v;
    if (i < NN) g_ptr[i] = excl;
    if (threadIdx.x == 1023) g_bsum[blockIdx.x] = excl + v;
}
__global__ void scan2_kernel() {
    __shared__ int ws[4];
    const int t = threadIdx.x;
    const int lane = t & 31;
    const int wid  = t >> 5;
    int v = (t < NB_SCAN) ? g_bsum[t] : 0;
    int incl = v;
    #pragma unroll
    for (int o = 1; o < 32; o <<= 1) {
        int s = __shfl_up_sync(0xFFFFFFFFu, incl, o);
        if (lane >= o) incl += s;
    }
    if (lane == 31) ws[wid] = incl;
    __syncthreads();
    int add = 0;
    #pragma unroll
    for (int w = 0; w < 4; w++) if (w < wid) add += ws[w];
    int excl = add + incl - v;
    __syncthreads();
    if (t < NB_SCAN) g_bsum[t] = excl;
}
__global__ void scan3_kernel() {
    int i = blockIdx.x * 1024 + threadIdx.x;
    if (i == 0) g_ptr[NN] = NE;
    if (i < NN) {
        g_ptr[i] += g_bsum[blockIdx.x];
        int d = g_deg[i];
        g_invc[i] = 1.0f / (float)(d < 1 ? 1 : d);
        g_cursor[i] = 0;
    }
}
__global__ void build_kernel(const int* __restrict__ src, const int* __restrict__ dst) {
    int e = blockIdx.x * blockDim.x + threadIdx.x;
    if (e < NE) {
        int d   = dst[e];
        int pos = atomicAdd(&g_cursor[d], 1);
        g_csr[g_ptr[d] + pos] = src[e];
    }
}

// ---------------- fp32 -> hi/lo bf16 + fp16 shadow for x ----------------
__global__ void split_kernel(const float* __restrict__ in,
                             __nv_bfloat16* __restrict__ hi,
                             __nv_bfloat16* __restrict__ lo,
                             __half* __restrict__ f16) {
    int i = blockIdx.x * blockDim.x + threadIdx.x;
    if (i < NN * C / 4) {
        float4 v = ((const float4*)in)[i];
        __nv_bfloat162 h01, h23, l01, l23;
        split1(v.x, h01.x, l01.x); split1(v.y, h01.y, l01.y);
        split1(v.z, h23.x, l23.x); split1(v.w, h23.y, l23.y);
        ((__nv_bfloat162*)hi)[i * 2]     = h01;
        ((__nv_bfloat162*)hi)[i * 2 + 1] = h23;
        ((__nv_bfloat162*)lo)[i * 2]     = l01;
        ((__nv_bfloat162*)lo)[i * 2 + 1] = l23;
        __half2 f01 = __floats2half2_rn(v.x, v.y);
        __half2 f23 = __floats2half2_rn(v.z, v.w);
        ((__half2*)f16)[i * 2]     = f01;
        ((__half2*)f16)[i * 2 + 1] = f23;
    }
}

// ---------------- weight prep: 5 pairs, grid (128, 5) ----------------
__global__ void wprep_kernel(const float* __restrict__ W1l, const float* __restrict__ W1r,
                             const float* __restrict__ W2l, const float* __restrict__ W2r,
                             const float* __restrict__ Wd) {
    const int n = blockIdx.x;
    const int which = blockIdx.y;
    const float* W =
        (which == 0) ? W1l : (which == 1) ? W1r :
        (which == 2) ? W2l : (which == 3) ? W2r : Wd;
    for (int k = threadIdx.x; k < 128; k += blockDim.x) {
        float v = W[k * C + n];
        __nv_bfloat16 h, l;
        split1(v, h, l);
        g_wh[which][n * 128 + k] = h;
        g_wl[which][n * 128 + k] = l;
    }
}

// ---------------- aggregation: warp per node, fp16 gather (256B/row) ----------------
__global__ void agg_kernel(const __half* __restrict__ feat) {
    int gw = (blockIdx.x * blockDim.x + threadIdx.x) >> 5;
    if (gw >= NN) return;
    int lane = threadIdx.x & 31;
    int beg = g_ptr[gw], end = g_ptr[gw + 1];
    float4 acc = make_float4(0.f, 0.f, 0.f, 0.f);
    int e = beg;
    for (; e + 4 <= end; e += 4) {
        int s0 = g_csr[e], s1 = g_csr[e + 1], s2 = g_csr[e + 2], s3 = g_csr[e + 3];
        uint2 u0 = *reinterpret_cast<const uint2*>(feat + (size_t)s0 * C + lane * 4);
        uint2 u1 = *reinterpret_cast<const uint2*>(feat + (size_t)s1 * C + lane * 4);
        uint2 u2 = *reinterpret_cast<const uint2*>(feat + (size_t)s2 * C + lane * 4);
        uint2 u3 = *reinterpret_cast<const uint2*>(feat + (size_t)s3 * C + lane * 4);
        #pragma unroll
        for (int q = 0; q < 4; q++) {
            uint2 u = (q == 0) ? u0 : (q == 1) ? u1 : (q == 2) ? u2 : u3;
            float2 a = __half22float2(*(__half2*)&u.x);
            float2 b = __half22float2(*(__half2*)&u.y);
            acc.x += a.x; acc.y += a.y; acc.z += b.x; acc.w += b.y;
        }
    }
    for (; e < end; e++) {
        int s = g_csr[e];
        uint2 u = *reinterpret_cast<const uint2*>(feat + (size_t)s * C + lane * 4);
        float2 a = __half22float2(*(__half2*)&u.x);
        float2 b = __half22float2(*(__half2*)&u.y);
        acc.x += a.x; acc.y += a.y; acc.z += b.x; acc.w += b.y;
    }
    float iv = g_invc[gw];
    acc.x *= iv; acc.y *= iv; acc.z *= iv; acc.w *= iv;
    __nv_bfloat162 h01, h23, l01, l23;
    split1(acc.x, h01.x, l01.x); split1(acc.y, h01.y, l01.y);
    split1(acc.z, h23.x, l23.x); split1(acc.w, h23.y, l23.y);
    size_t off = (size_t)gw * C + lane * 4;
    ((__nv_bfloat162*)(g_aggh + off))[0] = h01;
    ((__nv_bfloat162*)(g_aggh + off))[1] = h23;
    ((__nv_bfloat162*)(g_aggl + off))[0] = l01;
    ((__nv_bfloat162*)(g_aggl + off))[1] = l23;
}

// ---------------- cp.async-pipelined split-bf16 GEMM (K=128) ----------------
// D[128,128] = A[128,128] @ B^T via (AhBh + AhBl + AlBh), fp32 accum.
// MODE 0: R-branch  -> outF = acc                      (no bias)
// MODE 1: L layer1  -> relu(acc + P + bias) -> fp16 + hi/lo
// MODE 2: L layer2  -> relu(acc + P + bias) -> hi/lo
// MODE 3: decoder   -> alpha*(acc + bias) + (1-alpha)*xres -> f32
template <int MODE>
__global__ __launch_bounds__(256) void gemm_mma_kernel(
    const __nv_bfloat16* __restrict__ Ah, const __nv_bfloat16* __restrict__ Al,
    const __nv_bfloat16* __restrict__ Bh, const __nv_bfloat16* __restrict__ Bl,
    const float* __restrict__ P, const float* __restrict__ bias,
    const float* __restrict__ xres, const float* __restrict__ alphaPtr,
    float* __restrict__ outF, __half* __restrict__ outF16,
    __nv_bfloat16* __restrict__ outH, __nv_bfloat16* __restrict__ outL)
{
    constexpr int NCH = 4;
    extern __shared__ __align__(128) char smem[];
    const uint32_t us = s2u(smem);

    const int tid  = threadIdx.x;
    const int wid  = tid >> 5;
    const int lane = tid & 31;
    const int m0   = blockIdx.x * 128;
    const int m0w  = (wid >> 1) * 32;
    const int n0w  = (wid & 1) * 64;

    const int lrow = tid >> 1;
    const int c16a = (tid & 1) * 2;

    float acc[2][8][4];
    #pragma unroll
    for (int i = 0; i < 2; i++)
        #pragma unroll
        for (int j = 0; j < 8; j++)
            #pragma unroll
            for (int q = 0; q < 4; q++) acc[i][j][q] = 0.f;

    auto issue = [&](int kc, int buf) {
        const char* pAh = (const char*)Ah + (size_t)(m0 + lrow) * 256 + kc * 64;
        const char* pAl = (const char*)Al + (size_t)(m0 + lrow) * 256 + kc * 64;
        const char* pBh = (const char*)Bh + (size_t)lrow * 256 + kc * 64;
        const char* pBl = (const char*)Bl + (size_t)lrow * 256 + kc * 64;
        const uint32_t sb = us + buf * 32768;
        #pragma unroll
        for (int j = 0; j < 2; j++) {
            const int c16 = c16a + j;
            const uint32_t so = swz64((uint32_t)(lrow * 64 + c16 * 16));
            cp16(sb + so,          pAh + c16 * 16);
            cp16(sb + 8192 + so,   pAl + c16 * 16);
            cp16(sb + 16384 + so,  pBh + c16 * 16);
            cp16(sb + 24576 + so,  pBl + c16 * 16);
        }
        asm volatile("cp.async.commit_group;" ::: "memory");
    };

    issue(0, 0);
    for (int kc = 0; kc < NCH; kc++) {
        if (kc + 1 < NCH) {
            issue(kc + 1, (kc + 1) & 1);
            asm volatile("cp.async.wait_group 1;" ::: "memory");
        } else {
            asm volatile("cp.async.wait_group 0;" ::: "memory");
        }
        __syncthreads();
        const uint32_t sb = us + (kc & 1) * 32768;
        #pragma unroll
        for (int s = 0; s < 2; s++) {
            uint32_t aH[2][4], aL[2][4], bb[4][4];
            #pragma unroll
            for (int sub = 0; sub < 2; sub++) {
                const uint32_t off = swz64((uint32_t)(
                    (m0w + sub * 16 + (lane & 15)) * 64 + s * 32 + (lane >> 4) * 16));
                ldsm4(aH[sub], sb + off);
                ldsm4(aL[sub], sb + 8192 + off);
            }
            uint32_t offb[4];
            #pragma unroll
            for (int p = 0; p < 4; p++) {
                offb[p] = swz64((uint32_t)(
                    (n0w + p * 16 + (lane & 7) + ((lane >> 4) << 3)) * 64 +
                    s * 32 + ((lane >> 3) & 1) * 16));
                ldsm4(bb[p], sb + 16384 + offb[p]);
            }
            #pragma unroll
            for (int sub = 0; sub < 2; sub++)
                #pragma unroll
                for (int p = 0; p < 4; p++) {
                    mma16816(acc[sub][p * 2 + 0], aH[sub], &bb[p][0]);
                    mma16816(acc[sub][p * 2 + 1], aH[sub], &bb[p][2]);
                }
            #pragma unroll
            for (int sub = 0; sub < 2; sub++)
                #pragma unroll
                for (int p = 0; p < 4; p++) {
                    mma16816(acc[sub][p * 2 + 0], aL[sub], &bb[p][0]);
                    mma16816(acc[sub][p * 2 + 1], aL[sub], &bb[p][2]);
                }
            #pragma unroll
            for (int p = 0; p < 4; p++)
                ldsm4(bb[p], sb + 24576 + offb[p]);
            #pragma unroll
            for (int sub = 0; sub < 2; sub++)
                #pragma unroll
                for (int p = 0; p < 4; p++) {
                    mma16816(acc[sub][p * 2 + 0], aH[sub], &bb[p][0]);
                    mma16816(acc[sub][p * 2 + 1], aH[sub], &bb[p][2]);
                }
        }
        __syncthreads();
    }

    // ---------------- epilogue ----------------
    float al = 0.f, om = 0.f;
    if (MODE == 3) { al = *alphaPtr; om = 1.0f - al; }
    const int ccol0 = n0w + (lane & 3) * 2;
    #pragma unroll
    for (int sub = 0; sub < 2; sub++) {
        const int rbase = m0 + m0w + sub * 16 + (lane >> 2);
        #pragma unroll
        for (int f = 0; f < 8; f++) {
            const int col = ccol0 + f * 8;
            float bx = 0.f, by = 0.f;
            if (MODE != 0) { bx = bias[col]; by = bias[col + 1]; }
            #pragma unroll
            for (int half = 0; half < 2; half++) {
                const int r = rbase + half * 8;
                if (r >= NN) continue;
                float vx = acc[sub][f][half * 2 + 0] + bx;
                float vy = acc[sub][f][half * 2 + 1] + by;
                if (MODE == 0) {
                    *(float2*)(outF + (size_t)r * C + col) = make_float2(vx, vy);
                } else if (MODE == 1 || MODE == 2) {
                    const float2 pv = *(const float2*)(P + (size_t)r * C + col);
                    vx = fmaxf(vx + pv.x, 0.f);
                    vy = fmaxf(vy + pv.y, 0.f);
                    __nv_bfloat162 h2, l2;
                    split1(vx, h2.x, l2.x); split1(vy, h2.y, l2.y);
                    *(__nv_bfloat162*)(outH + (size_t)r * C + col) = h2;
                    *(__nv_bfloat162*)(outL + (size_t)r * C + col) = l2;
                    if (MODE == 1)
                        *(__half2*)(outF16 + (size_t)r * C + col) = __floats2half2_rn(vx, vy);
                } else {
                    const float2 xr = *(const float2*)(xres + (size_t)r * C + col);
                    float2 fv;
                    fv.x = al * vx + om * xr.x;
                    fv.y = al * vy + om * xr.y;
                    *(float2*)(outF + (size_t)r * C + col) = fv;
                }
            }
        }
    }
}

// ---------------- launch ----------------
extern "C" void kernel_launch(void* const* d_in, const int* in_sizes, int n_in,
                              void* d_out, int out_size)
{
    const float* x    = (const float*)d_in[0];
    const int*   ei   = (const int*)  d_in[1];
    const float* W1l  = (const float*)d_in[2];
    const float* b1   = (const float*)d_in[3];
    const float* W1r  = (const float*)d_in[4];
    const float* W2l  = (const float*)d_in[5];
    const float* b2   = (const float*)d_in[6];
    const float* W2r  = (const float*)d_in[7];
    const float* Wd   = (const float*)d_in[8];
    const float* bd   = (const float*)d_in[9];
    const float* alph = (const float*)d_in[10];
    float* out = (float*)d_out;

    const int* src = ei;
    const int* dst = ei + NE;

    float *p1, *p2;
    int* degp;
    __half *xf16, *h1f16;
    __nv_bfloat16 *xh, *xl, *aggh, *aggl, *h1h, *h1l, *h2h, *h2l;
    cudaGetSymbolAddress((void**)&degp, g_deg);
    cudaGetSymbolAddress((void**)&p1,   g_p1);
    cudaGetSymbolAddress((void**)&p2,   g_p2);
    cudaGetSymbolAddress((void**)&xf16, g_xf16);
    cudaGetSymbolAddress((void**)&h1f16,g_h1f16);
    cudaGetSymbolAddress((void**)&xh,   g_xh);
    cudaGetSymbolAddress((void**)&xl,   g_xl);
    cudaGetSymbolAddress((void**)&aggh, g_aggh);
    cudaGetSymbolAddress((void**)&aggl, g_aggl);
    cudaGetSymbolAddress((void**)&h1h,  g_h1h);
    cudaGetSymbolAddress((void**)&h1l,  g_h1l);
    cudaGetSymbolAddress((void**)&h2h,  g_h2h);
    cudaGetSymbolAddress((void**)&h2l,  g_h2l);
    __nv_bfloat16 *wh0, *wl0;
    cudaGetSymbolAddress((void**)&wh0, g_wh);
    cudaGetSymbolAddress((void**)&wl0, g_wl);
    auto WH = [&](int i) { return wh0 + (size_t)i * 128 * 128; };
    auto WL = [&](int i) { return wl0 + (size_t)i * 128 * 128; };

    static cudaStream_t s1 = nullptr;
    static cudaEvent_t ev0 = nullptr, evR1 = nullptr, evL1 = nullptr, evR2 = nullptr;
    if (s1 == nullptr) {
        cudaStreamCreateWithFlags(&s1, cudaStreamNonBlocking);
        cudaEventCreateWithFlags(&ev0,  cudaEventDisableTiming);
        cudaEventCreateWithFlags(&evR1, cudaEventDisableTiming);
        cudaEventCreateWithFlags(&evL1, cudaEventDisableTiming);
        cudaEventCreateWithFlags(&evR2, cudaEventDisableTiming);
    }

    const int SMEM_GEMM = 2 * 32768;
    static bool attrSet = false;
    if (!attrSet) {
        cudaFuncSetAttribute(gemm_mma_kernel<0>, cudaFuncAttributeMaxDynamicSharedMemorySize, SMEM_GEMM);
        cudaFuncSetAttribute(gemm_mma_kernel<1>, cudaFuncAttributeMaxDynamicSharedMemorySize, SMEM_GEMM);
        cudaFuncSetAttribute(gemm_mma_kernel<2>, cudaFuncAttributeMaxDynamicSharedMemorySize, SMEM_GEMM);
        cudaFuncSetAttribute(gemm_mma_kernel<3>, cudaFuncAttributeMaxDynamicSharedMemorySize, SMEM_GEMM);
        attrSet = true;
    }

    const int TB = 256;
    const int gE  = (NE + TB - 1) / TB;
    const int gAg = (NN * 32 + TB - 1) / TB;
    const int gM  = (NN + 127) / 128;
    const int gS  = (NN * C / 4 + TB - 1) / TB;
    const cudaStream_t s0 = (cudaStream_t)0;   // legacy default (capture) stream

    // fork side stream
    cudaEventRecord(ev0, s0);
    cudaStreamWaitEvent(s1, ev0, 0);

    // s1: prep + R-branch of layer 1  (independent of graph structure)
    split_kernel<<<gS, TB, 0, s1>>>(x, xh, xl, xf16);
    wprep_kernel<<<dim3(128, 5), 256, 0, s1>>>(W1l, W1r, W2l, W2r, Wd);
    gemm_mma_kernel<0><<<gM, 256, SMEM_GEMM, s1>>>(xh, xl, WH(1), WL(1),
                                                   nullptr, nullptr, nullptr, nullptr,
                                                   p1, nullptr, nullptr, nullptr);
    cudaEventRecord(evR1, s1);

    // s0: CSR build + aggregation layer 1
    cudaMemsetAsync(degp, 0, NN * sizeof(int), s0);
    count_kernel<<<gE, TB, 0, s0>>>(dst);
    scan1_kernel<<<NB_SCAN, 1024, 0, s0>>>();
    scan2_kernel<<<1, 128, 0, s0>>>();
    scan3_kernel<<<NB_SCAN, 1024, 0, s0>>>();
    build_kernel<<<gE, TB, 0, s0>>>(src, dst);
    agg_kernel<<<gAg, TB, 0, s0>>>(xf16);

    // join R1, then L-branch layer 1
    cudaStreamWaitEvent(s0, evR1, 0);
    gemm_mma_kernel<1><<<gM, 256, SMEM_GEMM, s0>>>(aggh, aggl, WH(0), WL(0),
                                                   p1, b1, nullptr, nullptr,
                                                   nullptr, h1f16, h1h, h1l);
    cudaEventRecord(evL1, s0);

    // s1: R-branch layer 2 (needs h1 hi/lo) — overlaps agg2
    cudaStreamWaitEvent(s1, evL1, 0);
    gemm_mma_kernel<0><<<gM, 256, SMEM_GEMM, s1>>>(h1h, h1l, WH(3), WL(3),
                                                   nullptr, nullptr, nullptr, nullptr,
                                                   p2, nullptr, nullptr, nullptr);
    cudaEventRecord(evR2, s1);

    // s0: aggregation layer 2
    agg_kernel<<<gAg, TB, 0, s0>>>(h1f16);

    // join R2, then L-branch layer 2 + decoder
    cudaStreamWaitEvent(s0, evR2, 0);
    gemm_mma_kernel<2><<<gM, 256, SMEM_GEMM, s0>>>(aggh, aggl, WH(2), WL(2),
                                                   p2, b2, nullptr, nullptr,
                                                   nullptr, nullptr, h2h, h2l);
    gemm_mma_kernel<3><<<gM, 256, SMEM_GEMM, s0>>>(h2h, h2l, WH(4), WL(4),
                                                   nullptr, bd, x, alph,
                                                   out, nullptr, nullptr, nullptr);

    (void)in_sizes; (void)n_in; (void)out_size;
}